// round 1
// baseline (speedup 1.0000x reference)
#include <cuda_runtime.h>

#define NN 2048
#define BB 4
#define THREADS 256
#define ROWS_PER_BLOCK 8   // 8 warps, 1 row each
#define BLOCKS_PER_BATCH (NN / ROWS_PER_BLOCK)   // 256

// Scratch: sin/cos of theta, float4 per (b, n)
__device__ float4 g_s[BB * NN];
__device__ float4 g_c[BB * NN];

__global__ void sincos_kernel(const float4* __restrict__ theta) {
    int idx = blockIdx.x * blockDim.x + threadIdx.x;
    if (idx >= BB * NN) return;
    float4 t = theta[idx];
    float4 s, c;
    __sincosf(t.x, &s.x, &c.x);
    __sincosf(t.y, &s.y, &c.y);
    __sincosf(t.z, &s.z, &c.z);
    __sincosf(t.w, &s.w, &c.w);
    g_s[idx] = s;
    g_c[idx] = c;
}

__global__ __launch_bounds__(THREADS)
void kuramoto_kernel(const float* __restrict__ W,
                     const float* __restrict__ alpha,
                     const float4* __restrict__ theta,
                     const float4* __restrict__ gamma,
                     float4* __restrict__ out) {
    extern __shared__ float4 sh[];      // s[NN], c[NN]
    float4* s_sh = sh;
    float4* c_sh = sh + NN;

    const int b    = blockIdx.x / BLOCKS_PER_BATCH;
    const int row0 = (blockIdx.x % BLOCKS_PER_BATCH) * ROWS_PER_BLOCK;
    const int base = b * NN;

    // Cooperative load of this batch's sin/cos table into smem (64 KB)
    for (int j = threadIdx.x; j < NN; j += THREADS) {
        s_sh[j] = g_s[base + j];
        c_sh[j] = g_c[base + j];
    }
    __syncthreads();

    const int warp = threadIdx.x >> 5;
    const int lane = threadIdx.x & 31;
    const int i    = row0 + warp;

    const float* __restrict__ Wrow = W     + (size_t)(base + i) * NN;
    const float* __restrict__ Arow = alpha + (size_t)(base + i) * NN;

    float P0 = 0.f, P1 = 0.f, P2 = 0.f, P3 = 0.f;
    float Q0 = 0.f, Q1 = 0.f, Q2 = 0.f, Q3 = 0.f;

    #pragma unroll 4
    for (int jj = 0; jj < NN / 32; ++jj) {
        const int j = lane + jj * 32;
        float w = __ldg(Wrow + j);
        float a = __ldg(Arow + j);
        float sa, ca;
        __sincosf(a, &sa, &ca);
        float Av = w * ca;   // W * cos(alpha)
        float Bv = w * sa;   // W * sin(alpha)
        float4 sj = s_sh[j];
        float4 cj = c_sh[j];
        // P_d += A*c_j + B*s_j ;  Q_d += A*s_j - B*c_j
        P0 = fmaf(Av, cj.x, P0); P0 = fmaf(Bv, sj.x, P0);
        P1 = fmaf(Av, cj.y, P1); P1 = fmaf(Bv, sj.y, P1);
        P2 = fmaf(Av, cj.z, P2); P2 = fmaf(Bv, sj.z, P2);
        P3 = fmaf(Av, cj.w, P3); P3 = fmaf(Bv, sj.w, P3);
        Q0 = fmaf(Av, sj.x, Q0); Q0 = fmaf(-Bv, cj.x, Q0);
        Q1 = fmaf(Av, sj.y, Q1); Q1 = fmaf(-Bv, cj.y, Q1);
        Q2 = fmaf(Av, sj.z, Q2); Q2 = fmaf(-Bv, cj.z, Q2);
        Q3 = fmaf(Av, sj.w, Q3); Q3 = fmaf(-Bv, cj.w, Q3);
    }

    // Warp butterfly reduction of the 8 partial sums
    #pragma unroll
    for (int off = 16; off > 0; off >>= 1) {
        P0 += __shfl_xor_sync(0xffffffffu, P0, off);
        P1 += __shfl_xor_sync(0xffffffffu, P1, off);
        P2 += __shfl_xor_sync(0xffffffffu, P2, off);
        P3 += __shfl_xor_sync(0xffffffffu, P3, off);
        Q0 += __shfl_xor_sync(0xffffffffu, Q0, off);
        Q1 += __shfl_xor_sync(0xffffffffu, Q1, off);
        Q2 += __shfl_xor_sync(0xffffffffu, Q2, off);
        Q3 += __shfl_xor_sync(0xffffffffu, Q3, off);
    }

    if (lane == 0) {
        float4 t  = theta[base + i];
        float4 g  = gamma[base + i];
        float4 si = g_s[base + i];
        float4 ci = g_c[base + i];
        const float invn = 1.0f / (float)NN;   // COUPLING / N

        // coupling_d = invn * (c_i*Q - s_i*P)
        float cp0 = invn * (ci.x * Q0 - si.x * P0);
        float cp1 = invn * (ci.y * Q1 - si.y * P1);
        float cp2 = invn * (ci.z * Q2 - si.z * P2);
        float cp3 = invn * (ci.w * Q3 - si.w * P3);

        // theta_next = theta + DT*(ATTRACTION*(gamma - theta) + coupling), DT=ATTRACTION=1
        float n0 = t.x + (g.x - t.x) + cp0;
        float n1 = t.y + (g.y - t.y) + cp1;
        float n2 = t.z + (g.z - t.z) + cp2;
        float n3 = t.w + (g.w - t.w) + cp3;

        float nrm = sqrtf(n0 * n0 + n1 * n1 + n2 * n2 + n3 * n3);
        float inv = 1.0f / fmaxf(nrm, 1e-6f);
        out[base + i] = make_float4(n0 * inv, n1 * inv, n2 * inv, n3 * inv);
    }
}

extern "C" void kernel_launch(void* const* d_in, const int* in_sizes, int n_in,
                              void* d_out, int out_size) {
    const float* theta = (const float*)d_in[0];   // [B, N, 4]
    const float* gamma = (const float*)d_in[1];   // [B, N, 4]
    const float* W     = (const float*)d_in[2];   // [B, N, N]
    const float* alpha = (const float*)d_in[3];   // [B, N, N]
    float* out = (float*)d_out;                   // [B, N, 4]

    // Phase 1: sin/cos of theta into device scratch
    sincos_kernel<<<(BB * NN + 255) / 256, 256>>>((const float4*)theta);

    // Phase 2: main streaming kernel (64 KB dynamic smem -> needs opt-in)
    const int smem = 2 * NN * (int)sizeof(float4);   // 65536
    cudaFuncSetAttribute(kuramoto_kernel,
                         cudaFuncAttributeMaxDynamicSharedMemorySize, smem);
    kuramoto_kernel<<<BB * BLOCKS_PER_BATCH, THREADS, smem>>>(
        W, alpha, (const float4*)theta, (const float4*)gamma, (float4*)out);
}

// round 2
// speedup vs baseline: 1.2753x; 1.2753x over previous
#include <cuda_runtime.h>

#define NN 2048
#define BB 4
#define THREADS 256
#define ROWS_PER_BLOCK 8                         // 8 warps, 1 row each
#define BLOCKS_PER_BATCH (NN / ROWS_PER_BLOCK)   // 256
#define CHUNK 512                                // j's resident in smem at once
#define NCHUNKS (NN / CHUNK)                     // 4

// Scratch: sin/cos of theta, float4 per (b, n)
__device__ float4 g_s[BB * NN];
__device__ float4 g_c[BB * NN];

__global__ void sincos_kernel(const float4* __restrict__ theta) {
    int idx = blockIdx.x * blockDim.x + threadIdx.x;
    if (idx >= BB * NN) return;
    float4 t = theta[idx];
    float4 s, c;
    __sincosf(t.x, &s.x, &c.x);
    __sincosf(t.y, &s.y, &c.y);
    __sincosf(t.z, &s.z, &c.z);
    __sincosf(t.w, &s.w, &c.w);
    g_s[idx] = s;
    g_c[idx] = c;
}

__global__ __launch_bounds__(THREADS, 7)
void kuramoto_kernel(const float* __restrict__ W,
                     const float* __restrict__ alpha,
                     const float4* __restrict__ gamma,
                     float4* __restrict__ out) {
    __shared__ float4 s_sh[CHUNK];   // 8 KB
    __shared__ float4 c_sh[CHUNK];   // 8 KB   -> 16 KB total

    const int b    = blockIdx.x / BLOCKS_PER_BATCH;
    const int row0 = (blockIdx.x % BLOCKS_PER_BATCH) * ROWS_PER_BLOCK;
    const int base = b * NN;

    const int warp = threadIdx.x >> 5;
    const int lane = threadIdx.x & 31;
    const int i    = row0 + warp;

    const float* __restrict__ Wrow = W     + (size_t)(base + i) * NN;
    const float* __restrict__ Arow = alpha + (size_t)(base + i) * NN;

    float P0 = 0.f, P1 = 0.f, P2 = 0.f, P3 = 0.f;
    float Q0 = 0.f, Q1 = 0.f, Q2 = 0.f, Q3 = 0.f;

    for (int ch = 0; ch < NCHUNKS; ++ch) {
        __syncthreads();   // protect previous chunk's smem before overwrite
        // Cooperative load of this chunk's sin/cos table (16 KB, L2-resident)
        #pragma unroll
        for (int t = 0; t < CHUNK; t += THREADS) {
            int idx = t + threadIdx.x;
            s_sh[idx] = g_s[base + ch * CHUNK + idx];
            c_sh[idx] = g_c[base + ch * CHUNK + idx];
        }
        __syncthreads();

        const float* __restrict__ Wc = Wrow + ch * CHUNK;
        const float* __restrict__ Ac = Arow + ch * CHUNK;

        #pragma unroll 4
        for (int jj = 0; jj < CHUNK / 32; ++jj) {
            const int j = jj * 32 + lane;
            float w = __ldg(Wc + j);
            float a = __ldg(Ac + j);
            float sa, ca;
            __sincosf(a, &sa, &ca);
            float Av = w * ca;   // W * cos(alpha)
            float Bv = w * sa;   // W * sin(alpha)
            float4 sj = s_sh[j];
            float4 cj = c_sh[j];
            // P_d += A*c_j + B*s_j ;  Q_d += A*s_j - B*c_j
            P0 = fmaf(Av, cj.x, P0); P0 = fmaf(Bv, sj.x, P0);
            P1 = fmaf(Av, cj.y, P1); P1 = fmaf(Bv, sj.y, P1);
            P2 = fmaf(Av, cj.z, P2); P2 = fmaf(Bv, sj.z, P2);
            P3 = fmaf(Av, cj.w, P3); P3 = fmaf(Bv, sj.w, P3);
            Q0 = fmaf(Av, sj.x, Q0); Q0 = fmaf(-Bv, cj.x, Q0);
            Q1 = fmaf(Av, sj.y, Q1); Q1 = fmaf(-Bv, cj.y, Q1);
            Q2 = fmaf(Av, sj.z, Q2); Q2 = fmaf(-Bv, cj.z, Q2);
            Q3 = fmaf(Av, sj.w, Q3); Q3 = fmaf(-Bv, cj.w, Q3);
        }
    }

    // Warp butterfly reduction of the 8 partial sums
    #pragma unroll
    for (int off = 16; off > 0; off >>= 1) {
        P0 += __shfl_xor_sync(0xffffffffu, P0, off);
        P1 += __shfl_xor_sync(0xffffffffu, P1, off);
        P2 += __shfl_xor_sync(0xffffffffu, P2, off);
        P3 += __shfl_xor_sync(0xffffffffu, P3, off);
        Q0 += __shfl_xor_sync(0xffffffffu, Q0, off);
        Q1 += __shfl_xor_sync(0xffffffffu, Q1, off);
        Q2 += __shfl_xor_sync(0xffffffffu, Q2, off);
        Q3 += __shfl_xor_sync(0xffffffffu, Q3, off);
    }

    if (lane == 0) {
        float4 g  = gamma[base + i];
        float4 si = g_s[base + i];
        float4 ci = g_c[base + i];
        const float invn = 1.0f / (float)NN;   // COUPLING / N

        // coupling_d = invn * (c_i*Q_d - s_i*P_d)
        // theta_next = theta + (gamma - theta) + coupling = gamma + coupling
        float n0 = g.x + invn * (ci.x * Q0 - si.x * P0);
        float n1 = g.y + invn * (ci.y * Q1 - si.y * P1);
        float n2 = g.z + invn * (ci.z * Q2 - si.z * P2);
        float n3 = g.w + invn * (ci.w * Q3 - si.w * P3);

        float nrm = sqrtf(n0 * n0 + n1 * n1 + n2 * n2 + n3 * n3);
        float inv = 1.0f / fmaxf(nrm, 1e-6f);
        out[base + i] = make_float4(n0 * inv, n1 * inv, n2 * inv, n3 * inv);
    }
}

extern "C" void kernel_launch(void* const* d_in, const int* in_sizes, int n_in,
                              void* d_out, int out_size) {
    const float* theta = (const float*)d_in[0];   // [B, N, 4]
    const float* gamma = (const float*)d_in[1];   // [B, N, 4]
    const float* W     = (const float*)d_in[2];   // [B, N, N]
    const float* alpha = (const float*)d_in[3];   // [B, N, N]
    float* out = (float*)d_out;                   // [B, N, 4]

    // Phase 1: sin/cos of theta into device scratch
    sincos_kernel<<<(BB * NN + 255) / 256, 256>>>((const float4*)theta);

    // Phase 2: main streaming kernel — 16 KB static smem, 7 CTAs/SM,
    // grid = 1024 <= 148*7 = single wave.
    kuramoto_kernel<<<BB * BLOCKS_PER_BATCH, THREADS>>>(
        W, alpha, (const float4*)gamma, (float4*)out);
}

// round 3
// speedup vs baseline: 1.4823x; 1.1624x over previous
#include <cuda_runtime.h>

#define NN 2048
#define BB 4
#define THREADS 128
#define WARPS 4
#define R 2                                     // rows per warp
#define ROWS_PER_BLOCK (WARPS * R)              // 8
#define BLOCKS_PER_BATCH (NN / ROWS_PER_BLOCK)  // 256
#define CHUNK 512
#define NCHUNKS (NN / CHUNK)                    // 4

typedef unsigned long long u64;

// Scratch: sin/cos of theta, float4 per (b, n)  (AoS: [s0 s1 s2 s3])
__device__ float4 g_s[BB * NN];
__device__ float4 g_c[BB * NN];

__global__ void sincos_kernel(const float4* __restrict__ theta) {
    int idx = blockIdx.x * blockDim.x + threadIdx.x;
    if (idx >= BB * NN) return;
    float4 t = theta[idx];
    float4 s, c;
    __sincosf(t.x, &s.x, &c.x);
    __sincosf(t.y, &s.y, &c.y);
    __sincosf(t.z, &s.z, &c.z);
    __sincosf(t.w, &s.w, &c.w);
    g_s[idx] = s;
    g_c[idx] = c;
}

__device__ __forceinline__ void fma2(u64& d, u64 a, u64 b) {
    asm("fma.rn.f32x2 %0, %1, %2, %0;" : "+l"(d) : "l"(a), "l"(b));
}
__device__ __forceinline__ u64 pack2(float lo, float hi) {
    u64 r;
    asm("mov.b64 %0, {%1, %2};" : "=l"(r) : "f"(lo), "f"(hi));
    return r;
}
__device__ __forceinline__ void unpack2(float& lo, float& hi, u64 v) {
    asm("mov.b64 {%0, %1}, %2;" : "=f"(lo), "=f"(hi) : "l"(v));
}
__device__ __forceinline__ u64 add2(u64 a, u64 b) {
    u64 r;
    asm("add.rn.f32x2 %0, %1, %2;" : "=l"(r) : "l"(a), "l"(b));
    return r;
}

__global__ __launch_bounds__(THREADS, 8)
void kuramoto_kernel(const float* __restrict__ W,
                     const float* __restrict__ alpha,
                     const float4* __restrict__ gamma,
                     float4* __restrict__ out) {
    __shared__ float4 s_sh[CHUNK];   // 8 KB
    __shared__ float4 c_sh[CHUNK];   // 8 KB

    const int b    = blockIdx.x / BLOCKS_PER_BATCH;
    const int row0 = (blockIdx.x % BLOCKS_PER_BATCH) * ROWS_PER_BLOCK;
    const int base = b * NN;

    const int warp = threadIdx.x >> 5;
    const int lane = threadIdx.x & 31;
    const int i0   = row0 + warp * R;   // this warp owns rows i0, i0+1

    const float* __restrict__ W0 = W     + (size_t)(base + i0) * NN;
    const float* __restrict__ A0 = alpha + (size_t)(base + i0) * NN;
    const float* __restrict__ W1 = W0 + NN;
    const float* __restrict__ A1 = A0 + NN;

    // Packed accumulators: [r][pair]  pair0=(d0,d1), pair1=(d2,d3)
    u64 P01[R], P23[R], Q01[R], Q23[R];
    #pragma unroll
    for (int r = 0; r < R; ++r) { P01[r] = 0; P23[r] = 0; Q01[r] = 0; Q23[r] = 0; }

    for (int ch = 0; ch < NCHUNKS; ++ch) {
        __syncthreads();
        #pragma unroll
        for (int t = 0; t < CHUNK; t += THREADS) {
            int idx = t + threadIdx.x;
            s_sh[idx] = g_s[base + ch * CHUNK + idx];
            c_sh[idx] = g_c[base + ch * CHUNK + idx];
        }
        __syncthreads();

        const float* __restrict__ W0c = W0 + ch * CHUNK;
        const float* __restrict__ A0c = A0 + ch * CHUNK;
        const float* __restrict__ W1c = W1 + ch * CHUNK;
        const float* __restrict__ A1c = A1 + ch * CHUNK;

        #pragma unroll
        for (int jj = 0; jj < CHUNK / 128; ++jj) {      // 4 iters, 128 j per iter
            const int j0 = jj * 128 + lane;
            // Batch all global loads first (16 LDG.32 in flight)
            float wv[R][4], av[R][4];
            #pragma unroll
            for (int k = 0; k < 4; ++k) {
                wv[0][k] = __ldg(W0c + j0 + 32 * k);
                av[0][k] = __ldg(A0c + j0 + 32 * k);
                wv[1][k] = __ldg(W1c + j0 + 32 * k);
                av[1][k] = __ldg(A1c + j0 + 32 * k);
            }
            #pragma unroll
            for (int k = 0; k < 4; ++k) {
                const int j = j0 + 32 * k;
                // LDS.128 -> two packed f32x2 operands each, no repacking
                const ulonglong2 sp = *reinterpret_cast<const ulonglong2*>(&s_sh[j]);
                const ulonglong2 cp = *reinterpret_cast<const ulonglong2*>(&c_sh[j]);
                #pragma unroll
                for (int r = 0; r < R; ++r) {
                    float sa, ca;
                    __sincosf(av[r][k], &sa, &ca);
                    const float Av = wv[r][k] * ca;     // W * cos(alpha)
                    const float Bv = wv[r][k] * sa;     // W * sin(alpha)
                    const u64 Av2  = pack2(Av, Av);
                    const u64 Bv2  = pack2(Bv, Bv);
                    const u64 nBv2 = pack2(-Bv, -Bv);
                    // P += Av*c + Bv*s ; Q += Av*s - Bv*c   (packed over d-pairs)
                    fma2(P01[r], Av2, cp.x);  fma2(P01[r], Bv2, sp.x);
                    fma2(P23[r], Av2, cp.y);  fma2(P23[r], Bv2, sp.y);
                    fma2(Q01[r], Av2, sp.x);  fma2(Q01[r], nBv2, cp.x);
                    fma2(Q23[r], Av2, sp.y);  fma2(Q23[r], nBv2, cp.y);
                }
            }
        }
    }

    // Warp butterfly reduction (packed 64-bit lanes)
    #pragma unroll
    for (int off = 16; off > 0; off >>= 1) {
        #pragma unroll
        for (int r = 0; r < R; ++r) {
            P01[r] = add2(P01[r], __shfl_xor_sync(0xffffffffu, P01[r], off));
            P23[r] = add2(P23[r], __shfl_xor_sync(0xffffffffu, P23[r], off));
            Q01[r] = add2(Q01[r], __shfl_xor_sync(0xffffffffu, Q01[r], off));
            Q23[r] = add2(Q23[r], __shfl_xor_sync(0xffffffffu, Q23[r], off));
        }
    }

    if (lane == 0) {
        const float invn = 1.0f / (float)NN;   // COUPLING / N
        #pragma unroll
        for (int r = 0; r < R; ++r) {
            const int i = i0 + r;
            float P0, P1, P2, P3, Q0, Q1, Q2, Q3;
            unpack2(P0, P1, P01[r]); unpack2(P2, P3, P23[r]);
            unpack2(Q0, Q1, Q01[r]); unpack2(Q2, Q3, Q23[r]);

            float4 g  = gamma[base + i];
            float4 si = g_s[base + i];
            float4 ci = g_c[base + i];

            // theta_next = gamma + (1/N)(c_i*Q - s_i*P)   (theta cancels)
            float n0 = g.x + invn * (ci.x * Q0 - si.x * P0);
            float n1 = g.y + invn * (ci.y * Q1 - si.y * P1);
            float n2 = g.z + invn * (ci.z * Q2 - si.z * P2);
            float n3 = g.w + invn * (ci.w * Q3 - si.w * P3);

            float nrm = sqrtf(n0 * n0 + n1 * n1 + n2 * n2 + n3 * n3);
            float inv = 1.0f / fmaxf(nrm, 1e-6f);
            out[base + i] = make_float4(n0 * inv, n1 * inv, n2 * inv, n3 * inv);
        }
    }
}

extern "C" void kernel_launch(void* const* d_in, const int* in_sizes, int n_in,
                              void* d_out, int out_size) {
    const float* theta = (const float*)d_in[0];   // [B, N, 4]
    const float* gamma = (const float*)d_in[1];   // [B, N, 4]
    const float* W     = (const float*)d_in[2];   // [B, N, N]
    const float* alpha = (const float*)d_in[3];   // [B, N, N]
    float* out = (float*)d_out;                   // [B, N, 4]

    sincos_kernel<<<(BB * NN + 255) / 256, 256>>>((const float4*)theta);

    // 1024 blocks x 128 threads, 2 rows/warp, 16 KB smem, cap 8 CTAs/SM
    kuramoto_kernel<<<BB * BLOCKS_PER_BATCH, THREADS>>>(
        W, alpha, (const float4*)gamma, (float4*)out);
}